// round 14
// baseline (speedup 1.0000x reference)
#include <cuda_runtime.h>
#include <cuda_bf16.h>

#define THREADS 128
#define T_STEPS 20
#define BETA 0.9f
#define THR 1.0f

typedef unsigned int u32;
typedef unsigned long long u64;

// ---- weight fragments in device globals (filled by prep kernel) ----
__device__ u64 gW2f[3 * 16 * 8 * 32];   // [s][nb16][kc8][lane]
__device__ u64 gW3f[3 * 8 * 8 * 32];    // [s][nb8][kc8][lane]
__device__ u64 gW1f[3 * 16 * 32];       // [s][nb16][lane]
__device__ u64 gW4f[3 * 2 * 4 * 32];    // [s][nb2][kc4][lane]

// ---- smem byte offsets (membranes + spike/x buffers) ----
#define MB1 0         // m1: 32 rows x 66 f2 x 8B = 16896
#define MB2 16896     // m2: 16896
#define MB3 33792     // m3: 32 x 34 f2 = 8704
#define MB4 42496     // m4: 32 x 8 f2 = 2048
#define SS1 44544     // 32 x 256B
#define SS2 52736     // 32 x 256B
#define SS3 60928     // 32 x 128B
#define SXS 65024     // 3 x 32 x 32B
#define SM_TOTAL 68096

__device__ __forceinline__ float bfv(float v) { return __bfloat162float(__float2bfloat16(v)); }
__device__ __forceinline__ u32 bfb(float v) { return (u32)__bfloat16_as_ushort(__float2bfloat16(v)); }

__device__ __forceinline__ float split_lvl(float v, int s) {
    float s0 = bfv(v);
    if (s == 0) return s0;
    float r = v - s0;
    float s1 = bfv(r);
    if (s == 1) return s1;
    return bfv(r - s1);
}

__global__ void prep_kernel(const float* __restrict__ w1g, const float* __restrict__ w2g,
                            const float* __restrict__ w3g, const float* __restrict__ w4g)
{
    int idx = blockIdx.x * blockDim.x + threadIdx.x;
    int lane = idx & 31;
    int nrow = lane >> 2;
    int koff = (lane & 3) * 2;
    if (idx < 12288) {             // W2: [3][16][8][32]
        int f = idx >> 5; int kc = f & 7; int nb = (f >> 3) & 15; int s = f >> 7;
        int n = nb * 8 + nrow; int k = kc * 16 + koff;
        u32 lo = bfb(split_lvl(w2g[n * 128 + k], s))     | (bfb(split_lvl(w2g[n * 128 + k + 1], s)) << 16);
        u32 hi = bfb(split_lvl(w2g[n * 128 + k + 8], s)) | (bfb(split_lvl(w2g[n * 128 + k + 9], s)) << 16);
        gW2f[idx] = (u64)lo | ((u64)hi << 32);
    } else if (idx < 18432) {      // W3: [3][8][8][32]
        int j = idx - 12288; int f = j >> 5; int kc = f & 7; int nb = (f >> 3) & 7; int s = f >> 6;
        int n = nb * 8 + nrow; int k = kc * 16 + koff;
        u32 lo = bfb(split_lvl(w3g[n * 128 + k], s))     | (bfb(split_lvl(w3g[n * 128 + k + 1], s)) << 16);
        u32 hi = bfb(split_lvl(w3g[n * 128 + k + 8], s)) | (bfb(split_lvl(w3g[n * 128 + k + 9], s)) << 16);
        gW3f[j] = (u64)lo | ((u64)hi << 32);
    } else if (idx < 19968) {      // W1: [3][16][32]
        int j = idx - 18432; int f = j >> 5; int nb = f & 15; int s = f >> 4;
        int n = nb * 8 + nrow; int k = koff;
        u32 lo = bfb(split_lvl(w1g[n * 16 + k], s))     | (bfb(split_lvl(w1g[n * 16 + k + 1], s)) << 16);
        u32 hi = bfb(split_lvl(w1g[n * 16 + k + 8], s)) | (bfb(split_lvl(w1g[n * 16 + k + 9], s)) << 16);
        gW1f[j] = (u64)lo | ((u64)hi << 32);
    } else if (idx < 20736) {      // W4: [3][2][4][32]
        int j = idx - 19968; int f = j >> 5; int kc = f & 3; int nb = (f >> 2) & 1; int s = f >> 3;
        int n = nb * 8 + nrow; int k = kc * 16 + koff;
        float a0 = (n < 10) ? w4g[n * 64 + k]     : 0.f;
        float a1 = (n < 10) ? w4g[n * 64 + k + 1] : 0.f;
        float a2 = (n < 10) ? w4g[n * 64 + k + 8] : 0.f;
        float a3 = (n < 10) ? w4g[n * 64 + k + 9] : 0.f;
        u32 lo = bfb(split_lvl(a0, s)) | (bfb(split_lvl(a1, s)) << 16);
        u32 hi = bfb(split_lvl(a2, s)) | (bfb(split_lvl(a3, s)) << 16);
        gW4f[j] = (u64)lo | ((u64)hi << 32);
    }
}

__device__ __forceinline__ void ldsm4(u32 a[4], u32 addr) {
    asm volatile("ldmatrix.sync.aligned.m8n8.x4.shared.b16 {%0,%1,%2,%3}, [%4];"
        : "=r"(a[0]), "=r"(a[1]), "=r"(a[2]), "=r"(a[3]) : "r"(addr));
}
__device__ __forceinline__ void mma_bf16(float d[4], const u32 a[4], u32 b0, u32 b1) {
    asm volatile("mma.sync.aligned.m16n8k16.row.col.f32.bf16.bf16.f32 "
        "{%0,%1,%2,%3}, {%4,%5,%6,%7}, {%8,%9}, {%0,%1,%2,%3};"
        : "+f"(d[0]), "+f"(d[1]), "+f"(d[2]), "+f"(d[3])
        : "r"(a[0]), "r"(a[1]), "r"(a[2]), "r"(a[3]), "r"(b0), "r"(b1));
}
__device__ __forceinline__ void sts32(u32 addr, u32 v) {
    asm volatile("st.shared.b32 [%0], %1;" :: "r"(addr), "r"(v) : "memory");
}

// LIF with membranes in smem (float2 rows r_ and r_+8); same fp32 op order as before.
__device__ __forceinline__ void lif4s(float2* mlo, float2* mhi, const float* d, float s[4]) {
    float2 lo = *mlo, hi = *mhi;
    float mem[4] = {lo.x, lo.y, hi.x, hi.y};
#pragma unroll
    for (int e = 0; e < 4; e++) {
        float m = mem[e];
        float reset = (m > THR) ? 1.0f : 0.0f;
        m = fmaf(BETA, m, d[e]) - reset;
        mem[e] = m;
        s[e] = (m > THR) ? 1.0f : 0.0f;
    }
    *mlo = make_float2(mem[0], mem[1]);
    *mhi = make_float2(mem[2], mem[3]);
}
__device__ __forceinline__ u32 packs(float a, float b) {
    return (a != 0.0f ? 0x3F80u : 0u) | (b != 0.0f ? 0x3F800000u : 0u);
}

__global__ void __launch_bounds__(THREADS, 3)
snn_mma_kernel(const float* __restrict__ x,
               float* __restrict__ out,
               int Btot)
{
    extern __shared__ __align__(16) char sm[];
    u32 smb;
    asm("{ .reg .u64 t; cvta.to.shared.u64 t, %1; cvt.u32.u64 %0, t; }"
        : "=r"(smb) : "l"(sm));

    const int tid  = threadIdx.x;
    const int w    = tid >> 5;
    const int lane = tid & 31;
    const int b0   = blockIdx.x * 32;

    // ---- zero membrane region ----
    for (int i = tid; i < 44544 / 4; i += THREADS)
        *(u32*)(sm + 4 * i) = 0u;

    // ---- lane roles ----
    const int arow = ((lane >> 3) & 1) * 8 + (lane & 7);
    const int ac   = lane >> 4;
    const int r_   = lane >> 2;
    const int c_   = lane & 3;
    const u32 rx8  = (u32)(lane & 7) << 4;

    const int Mw  = w >> 1, nb4 = w & 1;   // L4 role

    const u64* pW2 = gW2f + lane;
    const u64* pW3 = gW3f + lane;
    const u64* pW4 = gW4f + lane;

    // ---- hoist L1 B fragments ----
    u32 bw1[3][4][2];
#pragma unroll
    for (int lv = 0; lv < 3; lv++)
#pragma unroll
        for (int j = 0; j < 4; j++) {
            u64 q = gW1f[(lv * 16 + (w * 4 + j)) * 32 + lane];
            bw1[lv][j][0] = (u32)q;
            bw1[lv][j][1] = (u32)(q >> 32);
        }

    // ---- membrane smem pointers ----
    float2* m1p = (float2*)(sm + MB1);
    float2* m2p = (float2*)(sm + MB2);
    float2* m3p = (float2*)(sm + MB3);
    float2* m4p = (float2*)(sm + MB4);

    // ---- x staging role ----
    const int bsx = tid >> 2;
    const int f4  = (tid & 3) << 2;
    const u32 xbase = smb + SXS + (u32)(bsx * 32 + (((f4 >> 3) ^ (bsx & 1)) << 4) + (f4 & 7) * 2);

    auto stage_x = [&](const float4& v) {
        float e0 = v.x - bfv(v.x), e1 = v.y - bfv(v.y), e2 = v.z - bfv(v.z), e3 = v.w - bfv(v.w);
        float g0 = e0 - bfv(e0), g1 = e1 - bfv(e1), g2 = e2 - bfv(e2), g3 = e3 - bfv(e3);
        sts32(xbase,            bfb(v.x) | (bfb(v.y) << 16));
        sts32(xbase + 4,        bfb(v.z) | (bfb(v.w) << 16));
        sts32(xbase + 1024,     bfb(e0) | (bfb(e1) << 16));
        sts32(xbase + 1024 + 4, bfb(e2) | (bfb(e3) << 16));
        sts32(xbase + 2048,     bfb(g0) | (bfb(g1) << 16));
        sts32(xbase + 2048 + 4, bfb(g2) | (bfb(g3) << 16));
    };

    auto do_L1 = [&]() {   // warp M32 x N32, K=16, 6 split terms -> s1
        float acc[32];
#pragma unroll
        for (int i = 0; i < 32; i++) acc[i] = 0.f;
        const int la[6] = {0, 0, 1, 0, 1, 2};
        const int lb[6] = {0, 1, 0, 2, 1, 0};
#pragma unroll
        for (int M = 0; M < 2; M++) {
            u32 ax[3][4];
#pragma unroll
            for (int lv = 0; lv < 3; lv++)
                ldsm4(ax[lv], smb + SXS + (u32)(lv * 1024 + (16 * M + arow) * 32)
                              + (((u32)ac << 4) ^ ((u32)(arow & 1) << 4)));
#pragma unroll
            for (int s = 0; s < 6; s++)
#pragma unroll
                for (int j = 0; j < 4; j++)
                    mma_bf16(&acc[(M * 4 + j) * 4], ax[la[s]], bw1[lb[s]][j][0], bw1[lb[s]][j][1]);
        }
#pragma unroll
        for (int M = 0; M < 2; M++)
#pragma unroll
            for (int j = 0; j < 4; j++) {
                int fi = (16 * M + r_) * 66 + (4 * w + j) * 4 + c_;
                float s4[4];
                lif4s(&m1p[fi], &m1p[fi + 528], &acc[(M * 4 + j) * 4], s4);
                u32 a0 = smb + SS1 + (u32)((16 * M + r_) * 256)
                         + (((u32)(4 * w + j) << 4) ^ ((u32)r_ << 4)) + 4 * c_;
                sts32(a0, packs(s4[0], s4[1]));
                sts32(a0 + 2048, packs(s4[2], s4[3]));
            }
    };

    auto do_L4 = [&](int tt) {   // warp (Mw, nb4): M16 x N8, K=64
        float acc[4] = {0.f, 0.f, 0.f, 0.f};
#pragma unroll
        for (int kc = 0; kc < 4; kc++) {
            u32 a_[4];
            ldsm4(a_, smb + SS3 + (u32)((16 * Mw + arow) * 128)
                      + (((u32)(2 * kc + ac) << 4) ^ rx8));
#pragma unroll
            for (int s = 0; s < 3; s++) {
                u64 q = pW4[((s * 2 + nb4) * 4 + kc) * 32];
                mma_bf16(acc, a_, (u32)q, (u32)(q >> 32));
            }
        }
        int fi = (16 * Mw + r_) * 8 + nb4 * 4 + c_;
        float s4[4];
        lif4s(&m4p[fi], &m4p[fi + 64], acc, s4);
        size_t row0 = (size_t)tt * (size_t)Btot + (size_t)(b0 + 16 * Mw + r_);
        if (nb4 == 0) {
            *(float2*)(out + row0 * 10 + 2 * c_)       = make_float2(s4[0], s4[1]);
            *(float2*)(out + (row0 + 8) * 10 + 2 * c_) = make_float2(s4[2], s4[3]);
        } else if (c_ == 0) {
            *(float2*)(out + row0 * 10 + 8)       = make_float2(s4[0], s4[1]);
            *(float2*)(out + (row0 + 8) * 10 + 8) = make_float2(s4[2], s4[3]);
        }
    };

    // ===== prologue: zero-sync; stage x(0); L1(0) =====
    __syncthreads();
    {
        float4 v = *(const float4*)(x + ((size_t)0 * (size_t)Btot + (size_t)(b0 + bsx)) * 16 + f4);
        stage_x(v);
    }
    __syncthreads();
    do_L1();
    __syncthreads();

    for (int t = 0; t < T_STEPS; t++) {
        // ===== phase A: L4(t-1) + L2(t) + stage x(t+1) =====
        {
            float4 xv;
            if (t + 1 < T_STEPS)
                xv = *(const float4*)(x + ((size_t)(t + 1) * (size_t)Btot + (size_t)(b0 + bsx)) * 16 + f4);

            if (t > 0)
                do_L4(t - 1);

            float acc[32];
#pragma unroll
            for (int i = 0; i < 32; i++) acc[i] = 0.f;
#pragma unroll
            for (int kc = 0; kc < 8; kc++) {
                u32 a_[2][4];
#pragma unroll
                for (int M = 0; M < 2; M++)
                    ldsm4(a_[M], smb + SS1 + (u32)((16 * M + arow) * 256)
                                 + (((u32)(2 * kc + ac) << 4) ^ rx8));
#pragma unroll
                for (int s = 0; s < 3; s++) {
                    u64 q[4];
#pragma unroll
                    for (int j = 0; j < 4; j++)
                        q[j] = pW2[((s * 16 + (w * 4 + j)) * 8 + kc) * 32];
#pragma unroll
                    for (int M = 0; M < 2; M++)
#pragma unroll
                        for (int j = 0; j < 4; j++)
                            mma_bf16(&acc[(M * 4 + j) * 4], a_[M], (u32)q[j], (u32)(q[j] >> 32));
                }
            }
#pragma unroll
            for (int M = 0; M < 2; M++)
#pragma unroll
                for (int j = 0; j < 4; j++) {
                    int fi = (16 * M + r_) * 66 + (4 * w + j) * 4 + c_;
                    float s4[4];
                    lif4s(&m2p[fi], &m2p[fi + 528], &acc[(M * 4 + j) * 4], s4);
                    u32 a0 = smb + SS2 + (u32)((16 * M + r_) * 256)
                             + (((u32)(4 * w + j) << 4) ^ ((u32)r_ << 4)) + 4 * c_;
                    sts32(a0, packs(s4[0], s4[1]));
                    sts32(a0 + 2048, packs(s4[2], s4[3]));
                }

            if (t + 1 < T_STEPS)
                stage_x(xv);
        }
        __syncthreads();

        // ===== phase B: L3(t) + L1(t+1) =====
        {
            float acc[16];
#pragma unroll
            for (int i = 0; i < 16; i++) acc[i] = 0.f;
#pragma unroll
            for (int kc = 0; kc < 8; kc++) {
                u32 a_[2][4];
#pragma unroll
                for (int M = 0; M < 2; M++)
                    ldsm4(a_[M], smb + SS2 + (u32)((16 * M + arow) * 256)
                                 + (((u32)(2 * kc + ac) << 4) ^ rx8));
#pragma unroll
                for (int s = 0; s < 3; s++) {
                    u64 q0 = pW3[((s * 8 + (w * 2 + 0)) * 8 + kc) * 32];
                    u64 q1 = pW3[((s * 8 + (w * 2 + 1)) * 8 + kc) * 32];
#pragma unroll
                    for (int M = 0; M < 2; M++) {
                        mma_bf16(&acc[(M * 2 + 0) * 4], a_[M], (u32)q0, (u32)(q0 >> 32));
                        mma_bf16(&acc[(M * 2 + 1) * 4], a_[M], (u32)q1, (u32)(q1 >> 32));
                    }
                }
            }
#pragma unroll
            for (int M = 0; M < 2; M++)
#pragma unroll
                for (int nb = 0; nb < 2; nb++) {
                    int fi = (16 * M + r_) * 34 + (2 * w + nb) * 4 + c_;
                    float s4[4];
                    lif4s(&m3p[fi], &m3p[fi + 272], &acc[(M * 2 + nb) * 4], s4);
                    u32 a0 = smb + SS3 + (u32)((16 * M + r_) * 128)
                             + (((u32)(2 * w + nb) << 4) ^ ((u32)r_ << 4)) + 4 * c_;
                    sts32(a0, packs(s4[0], s4[1]));
                    sts32(a0 + 1024, packs(s4[2], s4[3]));
                }

            if (t + 1 < T_STEPS)
                do_L1();
        }
        __syncthreads();
    }

    // ===== epilogue: L4(T-1) =====
    do_L4(T_STEPS - 1);
}

extern "C" void kernel_launch(void* const* d_in, const int* in_sizes, int n_in,
                              void* d_out, int out_size) {
    const float* x  = (const float*)d_in[0];
    const float* w1 = (const float*)d_in[1];
    const float* w2 = (const float*)d_in[2];
    const float* w3 = (const float*)d_in[3];
    const float* w4 = (const float*)d_in[4];
    float* out = (float*)d_out;

    const int Btot = in_sizes[0] / (T_STEPS * 16);  // 65536

    prep_kernel<<<(20736 + 127) / 128, 128>>>(w1, w2, w3, w4);

    cudaFuncSetAttribute(snn_mma_kernel,
                         cudaFuncAttributeMaxDynamicSharedMemorySize,
                         SM_TOTAL);
    const int grid = Btot / 32;                     // 2048
    snn_mma_kernel<<<grid, THREADS, SM_TOTAL>>>(x, out, Btot);
}